// round 2
// baseline (speedup 1.0000x reference)
#include <cuda_runtime.h>
#include <cstddef>

#define N_AQI 35
#define N_MEO 18
#define NTOT  53
#define F_OUT 64
#define CTXD  60
#define BATCH 4096
#define NEGV  (-1e12f)
#define LALPHA 0.2f

// ---------------- batch-independent precomputed state ----------------
__device__ float g_bias[NTOT * NTOT];          // ctx_s + ctx_t + adj_norm * a[248]
__device__ unsigned int g_mask[NTOT][2];       // adjacency bitmask per row
__device__ float g_wsrc[2][2][26];             // [rowtype][colblock][k]  = W_u @ a[0:64]
__device__ float g_wdst[2][2][26];             // [coltype][rowblock][k]  = W_u @ a[124:188]

__global__ void precompute_kernel(
    const float* __restrict__ ctx,
    const float* __restrict__ adj_norm,
    const float* __restrict__ a_aa, const float* __restrict__ a_am,
    const float* __restrict__ a_ma, const float* __restrict__ a_mm,
    const float* __restrict__ W_ua, const float* __restrict__ W_um,
    const int*   __restrict__ adj)
{
    __shared__ float s_cs[NTOT][2];
    __shared__ float s_ct[NTOT][2];
    const int tid = threadIdx.x;
    const float* A[2][2] = {{a_aa, a_am}, {a_ma, a_mm}};

    for (int id = tid; id < NTOT * 4; id += blockDim.x) {
        int i = id % NTOT;
        int sel = id / NTOT;
        if (sel < 2) {
            int rb = (i < N_AQI) ? 0 : 1;
            const float* a = A[rb][sel];
            float acc = 0.f;
            for (int c = 0; c < CTXD; c++) acc += ctx[i * CTXD + c] * a[64 + c];
            s_cs[i][sel] = acc;
        } else {
            int rb = sel - 2;
            int cb = (i < N_AQI) ? 0 : 1;
            const float* a = A[rb][cb];
            float acc = 0.f;
            for (int c = 0; c < CTXD; c++) acc += ctx[i * CTXD + c] * a[188 + c];
            s_ct[i][rb] = acc;
        }
    }

    for (int id = tid; id < 2 * 2 * 2 * 26; id += blockDim.x) {
        int k = id % 26;
        int r = id / 26;
        int which = r >> 2;
        int t0 = (r >> 1) & 1;
        int t1 = r & 1;
        const float* W = (t0 == 0) ? W_ua : W_um;
        int K = (t0 == 0) ? 24 : 26;
        float acc = 0.f;
        if (k < K) {
            const float* a = (which == 0) ? A[t0][t1] : A[t1][t0];
            int off = (which == 0) ? 0 : 124;
            for (int f = 0; f < 64; f++) acc += W[k * 64 + f] * a[off + f];
        }
        if (which == 0) g_wsrc[t0][t1][k] = acc;
        else            g_wdst[t0][t1][k] = acc;
    }

    for (int i = tid; i < NTOT; i += blockDim.x) {
        unsigned int m0 = 0, m1 = 0;
        for (int j = 0; j < 32; j++)   if (adj[i * NTOT + j] > 0) m0 |= (1u << j);
        for (int j = 32; j < NTOT; j++) if (adj[i * NTOT + j] > 0) m1 |= (1u << (j - 32));
        g_mask[i][0] = m0; g_mask[i][1] = m1;
    }
    __syncthreads();

    for (int id = tid; id < NTOT * NTOT; id += blockDim.x) {
        int i = id / NTOT, j = id % NTOT;
        int rb = (i < N_AQI) ? 0 : 1;
        int cb = (j < N_AQI) ? 0 : 1;
        g_bias[id] = s_cs[i][cb] + s_ct[j][rb] + adj_norm[id] * A[rb][cb][248];
    }
}

// ---------------- packed fp32 helpers (sm_103a f32x2) ----------------
__device__ __forceinline__ unsigned long long fma2(unsigned long long a,
                                                   unsigned long long b,
                                                   unsigned long long c)
{
    unsigned long long d;
    asm("fma.rn.f32x2 %0, %1, %2, %3;" : "=l"(d) : "l"(a), "l"(b), "l"(c));
    return d;
}
__device__ __forceinline__ float lo32(unsigned long long v) { return __uint_as_float((unsigned)v); }
__device__ __forceinline__ float hi32(unsigned long long v) { return __uint_as_float((unsigned)(v >> 32)); }

// layout strides
#define PXT_STRIDE 60     // projxT[feat][node]: conflict-free for 128-bit lane loads
#define WT_STRIDE  20     // WT[feat][k]
#define ATT_STRIDE 56
#define FM_STRIDE  28     // meo full rows (aligned for 128-bit)

// ---------------- main kernel: one CTA per batch element ----------------
__global__ __launch_bounds__(256) void hgat_kernel(
    const float* __restrict__ aqi_inp, const float* __restrict__ meo_inp,
    const float* __restrict__ W_xa,    const float* __restrict__ W_xm,
    const float* __restrict__ aqi_idE, const float* __restrict__ aqi_monthE,
    const float* __restrict__ aqi_weekdayE, const float* __restrict__ aqi_hourE,
    const float* __restrict__ meo_windE, const float* __restrict__ meo_idE,
    const float* __restrict__ meo_monthE, const float* __restrict__ meo_weekdayE,
    const float* __restrict__ meo_hourE,
    const int* __restrict__ aqi_ex, const int* __restrict__ meo_ex,
    float* __restrict__ out)
{
    __shared__ float s_fullA[36 * 24];
    __shared__ float s_fullM[20 * FM_STRIDE];
    __shared__ float s_WxaT[64 * WT_STRIDE];
    __shared__ float s_WxmT[64 * WT_STRIDE];
    __shared__ float s_projxT[64 * PXT_STRIDE];     // transposed heter_attri [feat][node]
    __shared__ float s_attn[56 * ATT_STRIDE];
    __shared__ float s_S[NTOT * 2];
    __shared__ float s_T[NTOT * 2];

    const int tid = threadIdx.x;
    const int b = blockIdx.x;

    // ---- Phase 0: stage transposed weights, gather full rows, zero padded buffers ----
    #pragma unroll
    for (int it = 0; it < 4; it++) {
        int id = tid + it * 256;               // 1024 entries per matrix
        int f = id >> 4, k = id & 15;
        s_WxaT[f * WT_STRIDE + k] = W_xa[k * 64 + f];
        s_WxmT[f * WT_STRIDE + k] = W_xm[k * 64 + f];
    }
    // zero attn (3136 floats) and projxT (3840 floats) with 128-bit stores
    {
        float4 z = make_float4(0.f, 0.f, 0.f, 0.f);
        float4* za = reinterpret_cast<float4*>(s_attn);
        for (int i = tid; i < (56 * ATT_STRIDE) / 4; i += 256) za[i] = z;
        float4* zp = reinterpret_cast<float4*>(s_projxT);
        for (int i = tid; i < (64 * PXT_STRIDE) / 4; i += 256) zp[i] = z;
    }

    for (int id = tid; id < N_AQI * 24; id += 256) {
        int i = id / 24, c = id % 24;
        float v;
        if (c < 16) v = aqi_inp[((size_t)b * N_AQI + i) * 16 + c];
        else {
            int e = (c - 16) >> 1, comp = (c - 16) & 1;
            int ix = aqi_ex[((size_t)b * N_AQI + i) * 4 + e];
            const float* tab = (e == 0) ? aqi_idE : (e == 1) ? aqi_monthE
                             : (e == 2) ? aqi_weekdayE : aqi_hourE;
            v = tab[ix * 2 + comp];
        }
        s_fullA[i * 24 + c] = v;
    }
    for (int id = tid; id < N_MEO * 26; id += 256) {
        int i = id / 26, c = id % 26;
        float v;
        if (c < 16) v = meo_inp[((size_t)b * N_MEO + i) * 16 + c];
        else {
            int e = (c - 16) >> 1, comp = (c - 16) & 1;
            int ix = meo_ex[((size_t)b * N_MEO + i) * 5 + e];
            const float* tab = (e == 0) ? meo_windE : (e == 1) ? meo_idE
                             : (e == 2) ? meo_monthE : (e == 3) ? meo_weekdayE : meo_hourE;
            v = tab[ix * 2 + comp];
        }
        s_fullM[i * FM_STRIDE + c] = v;
    }
    __syncthreads();

    // ---- Phase 1: projxT = (full @ W_x)^T, packed f32x2 over k-pairs ----
    {
        const int f = tid & 63, rg = tid >> 6;       // 64 feats x 4 row-groups
        const float* wta = &s_WxaT[f * WT_STRIDE];
        const float* wtm = &s_WxmT[f * WT_STRIDE];

        unsigned long long accA[9];
        #pragma unroll
        for (int r = 0; r < 9; r++) accA[r] = 0ull;
        #pragma unroll
        for (int kg = 0; kg < 4; kg++) {
            ulonglong2 wv = *reinterpret_cast<const ulonglong2*>(wta + 4 * kg);
            #pragma unroll
            for (int r = 0; r < 9; r++) {
                int n = rg + 4 * r;
                ulonglong2 xv = *reinterpret_cast<const ulonglong2*>(&s_fullA[n * 24 + 4 * kg]);
                accA[r] = fma2(wv.x, xv.x, accA[r]);
                accA[r] = fma2(wv.y, xv.y, accA[r]);
            }
        }
        #pragma unroll
        for (int r = 0; r < 9; r++) {
            int n = rg + 4 * r;
            if (n < N_AQI) s_projxT[f * PXT_STRIDE + n] = lo32(accA[r]) + hi32(accA[r]);
        }

        unsigned long long accM[5];
        #pragma unroll
        for (int r = 0; r < 5; r++) accM[r] = 0ull;
        #pragma unroll
        for (int kg = 0; kg < 4; kg++) {
            ulonglong2 wv = *reinterpret_cast<const ulonglong2*>(wtm + 4 * kg);
            #pragma unroll
            for (int r = 0; r < 5; r++) {
                int n = rg + 4 * r;
                ulonglong2 xv = *reinterpret_cast<const ulonglong2*>(&s_fullM[n * FM_STRIDE + 4 * kg]);
                accM[r] = fma2(wv.x, xv.x, accM[r]);
                accM[r] = fma2(wv.y, xv.y, accM[r]);
            }
        }
        #pragma unroll
        for (int r = 0; r < 5; r++) {
            int n = rg + 4 * r;
            if (n < N_MEO) s_projxT[f * PXT_STRIDE + N_AQI + n] = lo32(accM[r]) + hi32(accM[r]);
        }
    }

    // ---- Phase 2: S[i][cb], T[j][rb] via folded weight vectors ----
    if (tid < NTOT * 4) {
        int i = tid % NTOT;
        int sel = tid / NTOT;
        int rt = (i < N_AQI) ? 0 : 1;
        const float* xr = (rt == 0) ? &s_fullA[i * 24] : &s_fullM[(i - N_AQI) * FM_STRIDE];
        int K = (rt == 0) ? 24 : 26;
        float acc = 0.f;
        if (sel < 2) {
            const float* wv = g_wsrc[rt][sel];
            for (int k = 0; k < K; k++) acc += xr[k] * wv[k];
            s_S[i * 2 + sel] = acc;
        } else {
            const float* wv = g_wdst[rt][sel - 2];
            for (int k = 0; k < K; k++) acc += xr[k] * wv[k];
            s_T[i * 2 + (sel - 2)] = acc;
        }
    }
    __syncthreads();

    // ---- Phase 3: masked leaky-relu scores + softmax, one warp per row ----
    {
        const int w = tid >> 5, lane = tid & 31;
        const int j1 = lane, j2 = lane + 32;
        const int cb1 = (j1 < N_AQI) ? 0 : 1;
        const int cb2 = (j2 < N_AQI) ? 0 : 1;
        const float t1_0 = s_T[j1 * 2 + 0], t1_1 = s_T[j1 * 2 + 1];
        const bool v2 = (j2 < NTOT);
        const float t2_0 = v2 ? s_T[j2 * 2 + 0] : 0.f;
        const float t2_1 = v2 ? s_T[j2 * 2 + 1] : 0.f;

        for (int i = w; i < NTOT; i += 8) {
            const int rb = (i < N_AQI) ? 0 : 1;
            const unsigned int m0 = g_mask[i][0], m1 = g_mask[i][1];
            float e1, e2;
            {
                float v = s_S[i * 2 + cb1] + (rb ? t1_1 : t1_0) + g_bias[i * NTOT + j1];
                v = (v >= 0.f) ? v : LALPHA * v;
                e1 = ((m0 >> j1) & 1u) ? v : NEGV;
            }
            if (v2) {
                float v = s_S[i * 2 + cb2] + (rb ? t2_1 : t2_0) + g_bias[i * NTOT + j2];
                v = (v >= 0.f) ? v : LALPHA * v;
                e2 = ((m1 >> (j2 - 32)) & 1u) ? v : NEGV;
            } else {
                e2 = -3.4e38f;
            }
            float mx = fmaxf(e1, e2);
            #pragma unroll
            for (int o = 16; o > 0; o >>= 1) mx = fmaxf(mx, __shfl_xor_sync(0xffffffffu, mx, o));
            float p1 = __expf(e1 - mx);
            float p2 = v2 ? __expf(e2 - mx) : 0.f;
            float sum = p1 + p2;
            #pragma unroll
            for (int o = 16; o > 0; o >>= 1) sum += __shfl_xor_sync(0xffffffffu, sum, o);
            float inv = 1.f / sum;
            s_attn[i * ATT_STRIDE + j1] = p1 * inv;
            if (v2) s_attn[i * ATT_STRIDE + j2] = p2 * inv;
        }
    }
    __syncthreads();

    // ---- Phase 4: out = attn @ proj_x, packed f32x2 over j-pairs ----
    {
        const int w = tid >> 5, lane = tid & 31;
        const float* px0p = &s_projxT[lane * PXT_STRIDE];
        const float* px1p = &s_projxT[(lane + 32) * PXT_STRIDE];

        unsigned long long acc0[7], acc1[7];
        #pragma unroll
        for (int r = 0; r < 7; r++) { acc0[r] = 0ull; acc1[r] = 0ull; }

        #pragma unroll 2
        for (int g = 0; g < 14; g++) {
            ulonglong2 px0 = *reinterpret_cast<const ulonglong2*>(px0p + 4 * g);
            ulonglong2 px1 = *reinterpret_cast<const ulonglong2*>(px1p + 4 * g);
            #pragma unroll
            for (int r = 0; r < 7; r++) {
                ulonglong2 at = *reinterpret_cast<const ulonglong2*>(
                    &s_attn[(w + 8 * r) * ATT_STRIDE + 4 * g]);
                acc0[r] = fma2(at.x, px0.x, acc0[r]);
                acc0[r] = fma2(at.y, px0.y, acc0[r]);
                acc1[r] = fma2(at.x, px1.x, acc1[r]);
                acc1[r] = fma2(at.y, px1.y, acc1[r]);
            }
        }

        #pragma unroll
        for (int r = 0; r < 7; r++) {
            int i = w + 8 * r;
            if (i < NTOT) {
                float* dst;
                if (i < N_AQI) dst = out + ((size_t)b * N_AQI + i) * 64;
                else dst = out + (size_t)BATCH * N_AQI * 64 + ((size_t)b * N_MEO + (i - N_AQI)) * 64;
                dst[lane]      = lo32(acc0[r]) + hi32(acc0[r]);
                dst[lane + 32] = lo32(acc1[r]) + hi32(acc1[r]);
            }
        }
    }
}

extern "C" void kernel_launch(void* const* d_in, const int* in_sizes, int n_in,
                              void* d_out, int out_size)
{
    const float* aqi_inp      = (const float*)d_in[0];
    const float* meo_inp      = (const float*)d_in[1];
    const float* context_feat = (const float*)d_in[2];
    const float* adj_norm     = (const float*)d_in[3];
    const float* aqi_idE      = (const float*)d_in[4];
    const float* aqi_monthE   = (const float*)d_in[5];
    const float* aqi_weekdayE = (const float*)d_in[6];
    const float* aqi_hourE    = (const float*)d_in[7];
    const float* meo_windE    = (const float*)d_in[8];
    const float* meo_idE      = (const float*)d_in[9];
    const float* meo_monthE   = (const float*)d_in[10];
    const float* meo_weekdayE = (const float*)d_in[11];
    const float* meo_hourE    = (const float*)d_in[12];
    const float* W_xa         = (const float*)d_in[13];
    const float* W_xm         = (const float*)d_in[14];
    const float* W_ua         = (const float*)d_in[15];
    const float* W_um         = (const float*)d_in[16];
    const float* a_aa         = (const float*)d_in[17];
    const float* a_am         = (const float*)d_in[18];
    const float* a_ma         = (const float*)d_in[19];
    const float* a_mm         = (const float*)d_in[20];
    const int*   aqi_ex       = (const int*)d_in[21];
    const int*   meo_ex       = (const int*)d_in[22];
    const int*   adj          = (const int*)d_in[23];
    float* out = (float*)d_out;

    precompute_kernel<<<1, 256>>>(context_feat, adj_norm,
                                  a_aa, a_am, a_ma, a_mm,
                                  W_ua, W_um, adj);
    hgat_kernel<<<BATCH, 256>>>(aqi_inp, meo_inp, W_xa, W_xm,
                                aqi_idE, aqi_monthE, aqi_weekdayE, aqi_hourE,
                                meo_windE, meo_idE, meo_monthE, meo_weekdayE, meo_hourE,
                                aqi_ex, meo_ex, out);
}

// round 3
// speedup vs baseline: 1.1850x; 1.1850x over previous
#include <cuda_runtime.h>
#include <cstddef>

#define N_AQI 35
#define N_MEO 18
#define NTOT  53
#define F_OUT 64
#define CTXD  60
#define BATCH 4096
#define NEGV  (-1e12f)
#define LALPHA 0.2f

// layout strides
#define PXT_STRIDE 60     // projxT[feat][node]
#define WT_STRIDE  20     // WT[feat][k]
#define ATT_STRIDE 56
#define FULL_STRIDE 28    // unified full-feature rows (conflict-free float4 per lane)

// ---------------- batch-independent precomputed state ----------------
__device__ float g_bias[NTOT * NTOT];
__device__ unsigned int g_mask[NTOT][2];
__device__ __align__(16) float g_wsrc[2][2][FULL_STRIDE];   // padded to 28, zeros beyond K
__device__ __align__(16) float g_wdst[2][2][FULL_STRIDE];
__device__ __align__(16) float g_WxaT[64 * WT_STRIDE];      // smem-ready transposed weights
__device__ __align__(16) float g_WxmT[64 * WT_STRIDE];

__global__ void precompute_kernel(
    const float* __restrict__ ctx,
    const float* __restrict__ adj_norm,
    const float* __restrict__ a_aa, const float* __restrict__ a_am,
    const float* __restrict__ a_ma, const float* __restrict__ a_mm,
    const float* __restrict__ W_ua, const float* __restrict__ W_um,
    const float* __restrict__ W_xa, const float* __restrict__ W_xm,
    const int*   __restrict__ adj)
{
    __shared__ float s_cs[NTOT][2];
    __shared__ float s_ct[NTOT][2];
    const int tid = threadIdx.x;
    const float* A[2][2] = {{a_aa, a_am}, {a_ma, a_mm}};

    for (int id = tid; id < NTOT * 4; id += blockDim.x) {
        int i = id % NTOT;
        int sel = id / NTOT;
        if (sel < 2) {
            int rb = (i < N_AQI) ? 0 : 1;
            const float* a = A[rb][sel];
            float acc = 0.f;
            for (int c = 0; c < CTXD; c++) acc += ctx[i * CTXD + c] * a[64 + c];
            s_cs[i][sel] = acc;
        } else {
            int rb = sel - 2;
            int cb = (i < N_AQI) ? 0 : 1;
            const float* a = A[rb][cb];
            float acc = 0.f;
            for (int c = 0; c < CTXD; c++) acc += ctx[i * CTXD + c] * a[188 + c];
            s_ct[i][rb] = acc;
        }
    }

    // folded weight-a vectors, padded to FULL_STRIDE with zeros
    for (int id = tid; id < 2 * 2 * 2 * FULL_STRIDE; id += blockDim.x) {
        int k = id % FULL_STRIDE;
        int r = id / FULL_STRIDE;
        int which = r >> 2;
        int t0 = (r >> 1) & 1;
        int t1 = r & 1;
        const float* W = (t0 == 0) ? W_ua : W_um;
        int K = (t0 == 0) ? 24 : 26;
        float acc = 0.f;
        if (k < K) {
            const float* a = (which == 0) ? A[t0][t1] : A[t1][t0];
            int off = (which == 0) ? 0 : 124;
            for (int f = 0; f < 64; f++) acc += W[k * 64 + f] * a[off + f];
        }
        if (which == 0) g_wsrc[t0][t1][k] = acc;
        else            g_wdst[t0][t1][k] = acc;
    }

    // transposed projection weights, smem-ready layout (stride 20, zeros k>=16)
    for (int id = tid; id < 64 * WT_STRIDE; id += blockDim.x) {
        int f = id / WT_STRIDE, k = id % WT_STRIDE;
        g_WxaT[id] = (k < 16) ? W_xa[k * 64 + f] : 0.f;
        g_WxmT[id] = (k < 16) ? W_xm[k * 64 + f] : 0.f;
    }

    for (int i = tid; i < NTOT; i += blockDim.x) {
        unsigned int m0 = 0, m1 = 0;
        for (int j = 0; j < 32; j++)   if (adj[i * NTOT + j] > 0) m0 |= (1u << j);
        for (int j = 32; j < NTOT; j++) if (adj[i * NTOT + j] > 0) m1 |= (1u << (j - 32));
        g_mask[i][0] = m0; g_mask[i][1] = m1;
    }
    __syncthreads();

    for (int id = tid; id < NTOT * NTOT; id += blockDim.x) {
        int i = id / NTOT, j = id % NTOT;
        int rb = (i < N_AQI) ? 0 : 1;
        int cb = (j < N_AQI) ? 0 : 1;
        g_bias[id] = s_cs[i][cb] + s_ct[j][rb] + adj_norm[id] * A[rb][cb][248];
    }
}

// ---------------- packed fp32 helpers (sm_103a f32x2) ----------------
__device__ __forceinline__ unsigned long long fma2(unsigned long long a,
                                                   unsigned long long b,
                                                   unsigned long long c)
{
    unsigned long long d;
    asm("fma.rn.f32x2 %0, %1, %2, %3;" : "=l"(d) : "l"(a), "l"(b), "l"(c));
    return d;
}
__device__ __forceinline__ float lo32(unsigned long long v) { return __uint_as_float((unsigned)v); }
__device__ __forceinline__ float hi32(unsigned long long v) { return __uint_as_float((unsigned)(v >> 32)); }

// ---------------- main kernel: one CTA per batch element ----------------
__global__ __launch_bounds__(256, 4) void hgat_kernel(
    const float* __restrict__ aqi_inp, const float* __restrict__ meo_inp,
    const float* __restrict__ aqi_idE, const float* __restrict__ aqi_monthE,
    const float* __restrict__ aqi_weekdayE, const float* __restrict__ aqi_hourE,
    const float* __restrict__ meo_windE, const float* __restrict__ meo_idE,
    const float* __restrict__ meo_monthE, const float* __restrict__ meo_weekdayE,
    const float* __restrict__ meo_hourE,
    const int* __restrict__ aqi_ex, const int* __restrict__ meo_ex,
    float* __restrict__ out)
{
    __shared__ float s_full[56 * FULL_STRIDE];      // rows 0-34 AQI, 35-52 MEO, pad cols zeroed inline
    __shared__ float s_WxaT[64 * WT_STRIDE];
    __shared__ float s_WxmT[64 * WT_STRIDE];
    __shared__ float s_projxT[64 * PXT_STRIDE];
    __shared__ float s_attn[56 * ATT_STRIDE];
    __shared__ float s_S[NTOT * 2];
    __shared__ float s_T[NTOT * 2];

    const int tid = threadIdx.x;
    const int b = blockIdx.x;

    // ---- Phase 0: stage weights (pure float4 memcpy), gather full rows, pad zeros ----
    {
        const float4* sa = reinterpret_cast<const float4*>(g_WxaT);
        const float4* sm = reinterpret_cast<const float4*>(g_WxmT);
        float4* da = reinterpret_cast<float4*>(s_WxaT);
        float4* dm = reinterpret_cast<float4*>(s_WxmT);
        #pragma unroll
        for (int it = 0; it < 2; it++) {
            int i = tid + it * 256;
            if (i < 320) { da[i] = sa[i]; dm[i] = sm[i]; }
        }
    }
    // zero required pad cells only: projxT cols 53..55 (all 64 feats), attn cols 53..55 (rows 0..55)
    if (tid < 192) {
        int f = tid / 3, c = 53 + tid % 3;
        s_projxT[f * PXT_STRIDE + c] = 0.f;
    } else if (tid < 192 + 56) {
        int row = tid - 192;
        s_attn[row * ATT_STRIDE + 53] = 0.f;
        s_attn[row * ATT_STRIDE + 54] = 0.f;
        s_attn[row * ATT_STRIDE + 55] = 0.f;
    }

    // AQI rows: 35 x 28 (cols 24..27 = 0)
    for (int id = tid; id < N_AQI * FULL_STRIDE; id += 256) {
        int i = id / FULL_STRIDE, c = id % FULL_STRIDE;
        float v = 0.f;
        if (c < 16) v = aqi_inp[((size_t)b * N_AQI + i) * 16 + c];
        else if (c < 24) {
            int e = (c - 16) >> 1, comp = (c - 16) & 1;
            int ix = aqi_ex[((size_t)b * N_AQI + i) * 4 + e];
            const float* tab = (e == 0) ? aqi_idE : (e == 1) ? aqi_monthE
                             : (e == 2) ? aqi_weekdayE : aqi_hourE;
            v = tab[ix * 2 + comp];
        }
        s_full[i * FULL_STRIDE + c] = v;
    }
    // MEO rows: 18 x 28 (cols 26..27 = 0)
    for (int id = tid; id < N_MEO * FULL_STRIDE; id += 256) {
        int i = id / FULL_STRIDE, c = id % FULL_STRIDE;
        float v = 0.f;
        if (c < 16) v = meo_inp[((size_t)b * N_MEO + i) * 16 + c];
        else if (c < 26) {
            int e = (c - 16) >> 1, comp = (c - 16) & 1;
            int ix = meo_ex[((size_t)b * N_MEO + i) * 5 + e];
            const float* tab = (e == 0) ? meo_windE : (e == 1) ? meo_idE
                             : (e == 2) ? meo_monthE : (e == 3) ? meo_weekdayE : meo_hourE;
            v = tab[ix * 2 + comp];
        }
        s_full[(N_AQI + i) * FULL_STRIDE + c] = v;
    }
    __syncthreads();

    // ---- Phase 1: projxT = (full @ W_x)^T, packed f32x2 over k-pairs ----
    {
        const int f = tid & 63, rg = tid >> 6;
        const float* wta = &s_WxaT[f * WT_STRIDE];
        const float* wtm = &s_WxmT[f * WT_STRIDE];

        unsigned long long accA[9];
        #pragma unroll
        for (int r = 0; r < 9; r++) accA[r] = 0ull;
        #pragma unroll
        for (int kg = 0; kg < 4; kg++) {
            ulonglong2 wv = *reinterpret_cast<const ulonglong2*>(wta + 4 * kg);
            #pragma unroll
            for (int r = 0; r < 9; r++) {
                int n = rg + 4 * r;
                ulonglong2 xv = *reinterpret_cast<const ulonglong2*>(&s_full[n * FULL_STRIDE + 4 * kg]);
                accA[r] = fma2(wv.x, xv.x, accA[r]);
                accA[r] = fma2(wv.y, xv.y, accA[r]);
            }
        }
        #pragma unroll
        for (int r = 0; r < 9; r++) {
            int n = rg + 4 * r;
            if (n < N_AQI) s_projxT[f * PXT_STRIDE + n] = lo32(accA[r]) + hi32(accA[r]);
        }

        unsigned long long accM[5];
        #pragma unroll
        for (int r = 0; r < 5; r++) accM[r] = 0ull;
        #pragma unroll
        for (int kg = 0; kg < 4; kg++) {
            ulonglong2 wv = *reinterpret_cast<const ulonglong2*>(wtm + 4 * kg);
            #pragma unroll
            for (int r = 0; r < 5; r++) {
                int n = rg + 4 * r;
                ulonglong2 xv = *reinterpret_cast<const ulonglong2*>(&s_full[(N_AQI + n) * FULL_STRIDE + 4 * kg]);
                accM[r] = fma2(wv.x, xv.x, accM[r]);
                accM[r] = fma2(wv.y, xv.y, accM[r]);
            }
        }
        #pragma unroll
        for (int r = 0; r < 5; r++) {
            int n = rg + 4 * r;
            if (n < N_MEO) s_projxT[f * PXT_STRIDE + N_AQI + n] = lo32(accM[r]) + hi32(accM[r]);
        }
    }

    // ---- Phase 2: S[i][cb], T[j][rb] via folded vectors, conflict-free float4 dots ----
    if (tid < NTOT * 4) {
        int i = tid % NTOT;
        int sel = tid / NTOT;
        int rt = (i < N_AQI) ? 0 : 1;
        const float4* xr = reinterpret_cast<const float4*>(&s_full[i * FULL_STRIDE]);
        const float4* wv = reinterpret_cast<const float4*>(
            (sel < 2) ? g_wsrc[rt][sel] : g_wdst[rt][sel - 2]);
        float acc = 0.f;
        #pragma unroll
        for (int m = 0; m < 7; m++) {
            float4 x = xr[m], w = wv[m];
            acc += x.x * w.x + x.y * w.y + x.z * w.z + x.w * w.w;
        }
        if (sel < 2) s_S[i * 2 + sel] = acc;
        else         s_T[i * 2 + (sel - 2)] = acc;
    }
    __syncthreads();

    // ---- Phase 3: masked leaky-relu scores + softmax, one warp per row ----
    {
        const int w = tid >> 5, lane = tid & 31;
        const int j1 = lane, j2 = lane + 32;
        const int cb1 = (j1 < N_AQI) ? 0 : 1;
        const int cb2 = (j2 < N_AQI) ? 0 : 1;
        const float t1_0 = s_T[j1 * 2 + 0], t1_1 = s_T[j1 * 2 + 1];
        const bool v2 = (j2 < NTOT);
        const float t2_0 = v2 ? s_T[j2 * 2 + 0] : 0.f;
        const float t2_1 = v2 ? s_T[j2 * 2 + 1] : 0.f;

        for (int i = w; i < NTOT; i += 8) {
            const int rb = (i < N_AQI) ? 0 : 1;
            const unsigned int m0 = g_mask[i][0], m1 = g_mask[i][1];
            float e1, e2;
            {
                float v = s_S[i * 2 + cb1] + (rb ? t1_1 : t1_0) + g_bias[i * NTOT + j1];
                v = (v >= 0.f) ? v : LALPHA * v;
                e1 = ((m0 >> j1) & 1u) ? v : NEGV;
            }
            if (v2) {
                float v = s_S[i * 2 + cb2] + (rb ? t2_1 : t2_0) + g_bias[i * NTOT + j2];
                v = (v >= 0.f) ? v : LALPHA * v;
                e2 = ((m1 >> (j2 - 32)) & 1u) ? v : NEGV;
            } else {
                e2 = -3.4e38f;
            }
            float mx = fmaxf(e1, e2);
            #pragma unroll
            for (int o = 16; o > 0; o >>= 1) mx = fmaxf(mx, __shfl_xor_sync(0xffffffffu, mx, o));
            float p1 = __expf(e1 - mx);
            float p2 = v2 ? __expf(e2 - mx) : 0.f;
            float sum = p1 + p2;
            #pragma unroll
            for (int o = 16; o > 0; o >>= 1) sum += __shfl_xor_sync(0xffffffffu, sum, o);
            float inv = 1.f / sum;
            s_attn[i * ATT_STRIDE + j1] = p1 * inv;
            if (v2) s_attn[i * ATT_STRIDE + j2] = p2 * inv;
        }
    }
    __syncthreads();

    // ---- Phase 4: out = attn @ proj_x, packed f32x2 over j-pairs ----
    {
        const int w = tid >> 5, lane = tid & 31;
        const float* px0p = &s_projxT[lane * PXT_STRIDE];
        const float* px1p = &s_projxT[(lane + 32) * PXT_STRIDE];

        unsigned long long acc0[7], acc1[7];
        #pragma unroll
        for (int r = 0; r < 7; r++) { acc0[r] = 0ull; acc1[r] = 0ull; }

        #pragma unroll 2
        for (int g = 0; g < 14; g++) {
            ulonglong2 px0 = *reinterpret_cast<const ulonglong2*>(px0p + 4 * g);
            ulonglong2 px1 = *reinterpret_cast<const ulonglong2*>(px1p + 4 * g);
            #pragma unroll
            for (int r = 0; r < 7; r++) {
                ulonglong2 at = *reinterpret_cast<const ulonglong2*>(
                    &s_attn[(w + 8 * r) * ATT_STRIDE + 4 * g]);
                acc0[r] = fma2(at.x, px0.x, acc0[r]);
                acc0[r] = fma2(at.y, px0.y, acc0[r]);
                acc1[r] = fma2(at.x, px1.x, acc1[r]);
                acc1[r] = fma2(at.y, px1.y, acc1[r]);
            }
        }

        #pragma unroll
        for (int r = 0; r < 7; r++) {
            int i = w + 8 * r;
            if (i < NTOT) {
                float* dst;
                if (i < N_AQI) dst = out + ((size_t)b * N_AQI + i) * 64;
                else dst = out + (size_t)BATCH * N_AQI * 64 + ((size_t)b * N_MEO + (i - N_AQI)) * 64;
                dst[lane]      = lo32(acc0[r]) + hi32(acc0[r]);
                dst[lane + 32] = lo32(acc1[r]) + hi32(acc1[r]);
            }
        }
    }
}

extern "C" void kernel_launch(void* const* d_in, const int* in_sizes, int n_in,
                              void* d_out, int out_size)
{
    const float* aqi_inp      = (const float*)d_in[0];
    const float* meo_inp      = (const float*)d_in[1];
    const float* context_feat = (const float*)d_in[2];
    const float* adj_norm     = (const float*)d_in[3];
    const float* aqi_idE      = (const float*)d_in[4];
    const float* aqi_monthE   = (const float*)d_in[5];
    const float* aqi_weekdayE = (const float*)d_in[6];
    const float* aqi_hourE    = (const float*)d_in[7];
    const float* meo_windE    = (const float*)d_in[8];
    const float* meo_idE      = (const float*)d_in[9];
    const float* meo_monthE   = (const float*)d_in[10];
    const float* meo_weekdayE = (const float*)d_in[11];
    const float* meo_hourE    = (const float*)d_in[12];
    const float* W_xa         = (const float*)d_in[13];
    const float* W_xm         = (const float*)d_in[14];
    const float* W_ua         = (const float*)d_in[15];
    const float* W_um         = (const float*)d_in[16];
    const float* a_aa         = (const float*)d_in[17];
    const float* a_am         = (const float*)d_in[18];
    const float* a_ma         = (const float*)d_in[19];
    const float* a_mm         = (const float*)d_in[20];
    const int*   aqi_ex       = (const int*)d_in[21];
    const int*   meo_ex       = (const int*)d_in[22];
    const int*   adj          = (const int*)d_in[23];
    float* out = (float*)d_out;

    precompute_kernel<<<1, 256>>>(context_feat, adj_norm,
                                  a_aa, a_am, a_ma, a_mm,
                                  W_ua, W_um, W_xa, W_xm, adj);
    hgat_kernel<<<BATCH, 256>>>(aqi_inp, meo_inp,
                                aqi_idE, aqi_monthE, aqi_weekdayE, aqi_hourE,
                                meo_windE, meo_idE, meo_monthE, meo_weekdayE, meo_hourE,
                                aqi_ex, meo_ex, out);
}